// round 16
// baseline (speedup 1.0000x reference)
#include <cuda_runtime.h>
#include <cuda_fp16.h>
#include <cstdint>
#include <cstddef>

#define N_NODES 50000
#define M_PAD   50048    // 391 * 128
#define NE      640000
#define ET      (NE + N_NODES)
#define D_IN    128
#define HID     64
#define HEADS   3
#define SLOPE   0.2f
#define EPS     1e-16f

#define SCAN_BLK 1024
#define NBLK     ((N_NODES + SCAN_BLK - 1) / SCAN_BLK)   // 49
#define ASTR     40      // smem row stride in halves (80 B)

// prep block ranges
#define XBLK ((N_NODES * D_IN / 4 + 255) / 256)          // convert x
#define WBLK (((HEADS * HID) * D_IN + 255) / 256)        // convert W
#define ZBLK ((N_NODES + 255) / 256)                     // zero counts

// ---------------- scratch (referenced ONLY from device code) ----------------
__device__ __half g_xh[(size_t)M_PAD * D_IN];
__device__ __half g_w1t[(HEADS * HID) * D_IN];
__device__ __half g_w2t[HID * (HEADS * HID)];
__device__ __half g_xwh[(size_t)N_NODES * HEADS * HID];
__device__ __half g_h1h[(size_t)M_PAD * HEADS * HID];
__device__ float  g_asrc[N_NODES * HEADS];
__device__ float  g_adst[N_NODES * HEADS];
__device__ int    g_counts[N_NODES];
__device__ int    g_offsets[N_NODES + 1];
__device__ int    g_cursor[N_NODES];
__device__ int    g_csr_src[ET];
__device__ int    g_blocksums[NBLK];
__device__ int    g_is64;

// ---------------- small helpers ----------------
__device__ __forceinline__ uint32_t smem_u32(const void* p) {
    return (uint32_t)__cvta_generic_to_shared(p);
}
__device__ __forceinline__ void cp16(uint32_t dst, const void* src) {
    asm volatile("cp.async.cg.shared.global [%0], [%1], 16;\n" :: "r"(dst), "l"(src));
}
__device__ __forceinline__ void cp_commit() {
    asm volatile("cp.async.commit_group;\n");
}
template <int N> __device__ __forceinline__ void cp_wait() {
    asm volatile("cp.async.wait_group %0;\n" :: "n"(N));
}
__device__ __forceinline__ void ldsm4(uint32_t& r0, uint32_t& r1, uint32_t& r2,
                                      uint32_t& r3, uint32_t addr) {
    asm volatile("ldmatrix.sync.aligned.m8n8.x4.shared.b16 {%0,%1,%2,%3}, [%4];\n"
                 : "=r"(r0), "=r"(r1), "=r"(r2), "=r"(r3) : "r"(addr));
}
__device__ __forceinline__ void mma_f16(float* d, const uint32_t* a, const uint32_t* b) {
    asm volatile(
        "mma.sync.aligned.m16n8k16.row.col.f32.f16.f16.f32 "
        "{%0,%1,%2,%3}, {%4,%5,%6,%7}, {%8,%9}, {%0,%1,%2,%3};\n"
        : "+f"(d[0]), "+f"(d[1]), "+f"(d[2]), "+f"(d[3])
        : "r"(a[0]), "r"(a[1]), "r"(a[2]), "r"(a[3]), "r"(b[0]), "r"(b[1]));
}

__device__ __forceinline__ int edge_at(const void* ei, long long idx) {
    if (g_is64) return (int)((const long long*)ei)[idx];
    return ((const int*)ei)[idx];
}

// ---------------- prep (main stream): convert x + convert W to fp16 ----------------
__global__ void prep_main_kernel(const float* __restrict__ x,
                                 const float* __restrict__ W1,
                                 const float* __restrict__ W2) {
    int b = blockIdx.x;
    int tid = threadIdx.x;
    if (b < XBLK) {
        int i = b * 256 + tid;
        if (i < N_NODES * D_IN / 4) {
            float4 v = *(const float4*)(x + 4 * (size_t)i);
            __half2* d = (__half2*)&g_xh[4 * (size_t)i];
            d[0] = __floats2half2_rn(v.x, v.y);
            d[1] = __floats2half2_rn(v.z, v.w);
        }
    } else {
        int i = (b - XBLK) * 256 + tid;
        if (i < (HEADS * HID) * D_IN) {
            int n = i / D_IN, k = i % D_IN;
            g_w1t[i] = __float2half_rn(W1[(size_t)k * (HEADS * HID) + n]);
        }
        if (i < HID * (HEADS * HID)) {
            int n = i / (HEADS * HID), k = i % (HEADS * HID);
            g_w2t[i] = __float2half_rn(W2[(size_t)k * HID + n]);
        }
    }
}

// ---------------- prep (side stream): probe + zero counts ----------------
__global__ void prep_side_kernel(const int* __restrict__ ei32) {
    int b = blockIdx.x;
    int tid = threadIdx.x;
    if (b == 0) {
        __shared__ int s_or[256];
        int acc = 0;
        for (int i = tid; i < 2048; i += 256) acc |= ei32[2 * i + 1];
        s_or[tid] = acc;
        __syncthreads();
        for (int s = 128; s > 0; s >>= 1) {
            if (tid < s) s_or[tid] |= s_or[tid + s];
            __syncthreads();
        }
        if (tid == 0) g_is64 = (s_or[0] == 0) ? 1 : 0;
    } else {
        int i = (b - 1) * 256 + tid;
        if (i < N_NODES) g_counts[i] = 0;
    }
}

// ---------------- CSR build ----------------
__global__ void count_kernel(const void* __restrict__ ei) {
    int e = blockIdx.x * blockDim.x + threadIdx.x;
    if (e >= ET) return;
    int dst = (e < NE) ? edge_at(ei, (long long)NE + e) : (e - NE);
    atomicAdd(&g_counts[dst], 1);
}

__global__ void scan_part_kernel() {
    __shared__ int warp_sums[32];
    int tid = threadIdx.x, lane = tid & 31, wid = tid >> 5;
    int idx = blockIdx.x * SCAN_BLK + tid;
    int v = (idx < N_NODES) ? g_counts[idx] : 0;
    int x = v;
    #pragma unroll
    for (int o = 1; o < 32; o <<= 1) {
        int y = __shfl_up_sync(0xffffffffu, x, o);
        if (lane >= o) x += y;
    }
    if (lane == 31) warp_sums[wid] = x;
    __syncthreads();
    if (wid == 0) {
        int w = warp_sums[lane];
        #pragma unroll
        for (int o = 1; o < 32; o <<= 1) {
            int y = __shfl_up_sync(0xffffffffu, w, o);
            if (lane >= o) w += y;
        }
        warp_sums[lane] = w;
    }
    __syncthreads();
    int warp_off = (wid > 0) ? warp_sums[wid - 1] : 0;
    int incl = x + warp_off;
    if (idx < N_NODES) g_offsets[idx] = incl - v;
    if (tid == SCAN_BLK - 1) g_blocksums[blockIdx.x] = incl;
}

// fixup with the block-sum scan folded in
__global__ void scan_fixup_kernel() {
    __shared__ int s_base, s_total;
    int tid = threadIdx.x;
    int b = blockIdx.x;
    if (tid < 32) {
        int v  = (tid < NBLK) ? g_blocksums[tid] : 0;
        int v2 = (32 + tid < NBLK) ? g_blocksums[32 + tid] : 0;
        int x = v;
        #pragma unroll
        for (int o = 1; o < 32; o <<= 1) {
            int y = __shfl_up_sync(0xffffffffu, x, o);
            if (tid >= o) x += y;
        }
        int sum0 = __shfl_sync(0xffffffffu, x, 31);
        int y2 = v2;
        #pragma unroll
        for (int o = 1; o < 32; o <<= 1) {
            int y = __shfl_up_sync(0xffffffffu, y2, o);
            if (tid >= o) y2 += y;
        }
        y2 += sum0;
        if (b == 0) {
            if (tid == 0) s_base = 0;
        } else {
            int idx = b - 1;
            int want = (idx < 32) ? idx : idx - 32;
            if (tid == want) s_base = (idx < 32) ? x : y2;
        }
        {
            int idxT = NBLK - 1;
            int wantT = (idxT < 32) ? idxT : idxT - 32;
            if (tid == wantT) s_total = (idxT < 32) ? x : y2;
        }
    }
    __syncthreads();
    int idx = b * SCAN_BLK + tid;
    if (idx < N_NODES) {
        int v = g_offsets[idx] + s_base;
        g_offsets[idx] = v;
        g_cursor[idx] = v;
    }
    if (b == NBLK - 1 && tid == 0) g_offsets[N_NODES] = s_total;
}

__global__ void scatter_kernel(const void* __restrict__ ei) {
    int e = blockIdx.x * blockDim.x + threadIdx.x;
    if (e >= ET) return;
    int src, dst;
    if (e < NE) {
        src = edge_at(ei, e);
        dst = edge_at(ei, (long long)NE + e);
    } else {
        src = e - NE; dst = e - NE;
    }
    int pos = atomicAdd(&g_cursor[dst], 1);
    g_csr_src[pos] = src;
}

// ---------------- fp16 GEMM with cp.async + ldmatrix + FUSED alpha epilogue ----------------
template <int LAYER>
__global__ __launch_bounds__(256)
void gemm_h_kernel(const float* __restrict__ a_src, const float* __restrict__ a_dst) {
    constexpr int N = (LAYER == 1) ? HEADS * HID : HID;
    constexpr int K = (LAYER == 1) ? D_IN : HEADS * HID;
    constexpr int H = (LAYER == 1) ? HEADS : 1;
    constexpr int KT = K / 32;
    const __half* A  = (LAYER == 1) ? g_xh : g_h1h;
    const __half* Bt = (LAYER == 1) ? g_w1t : g_w2t;
    constexpr int M = N_NODES;

    __shared__ __half As[2][128 * ASTR];
    __shared__ __half Bs[2][64 * ASTR];
    __shared__ float s_alpha[128][2][2];   // [row][warp_n][s1/s2]
    constexpr uint32_t stA = 128 * ASTR * 2;
    constexpr uint32_t stB = 64 * ASTR * 2;

    int tid = threadIdx.x;
    int lane = tid & 31, wid = tid >> 5;
    int warp_m = wid & 3, warp_n = wid >> 2;
    int m0 = blockIdx.x * 128, n0 = blockIdx.y * 64;
    int h = blockIdx.y;
    int g = lane >> 2, t = lane & 3;

    uint32_t as0 = smem_u32(&As[0][0]);
    uint32_t bs0 = smem_u32(&Bs[0][0]);

    uint32_t aaddr[2], baddr[2];
    #pragma unroll
    for (int am = 0; am < 2; am++)
        aaddr[am] = as0 + 2 * ((warp_m * 32 + am * 16 + ((lane >> 3) & 1) * 8 + (lane & 7)) * ASTR
                               + (lane >> 4) * 8);
    #pragma unroll
    for (int p = 0; p < 2; p++)
        baddr[p] = bs0 + 2 * ((warp_n * 32 + p * 16 + (lane >> 4) * 8 + (lane & 7)) * ASTR
                              + ((lane >> 3) & 1) * 8);

    int ar0 = tid >> 2;
    int ac  = (tid & 3) * 8;
    int br  = tid >> 2;
    const __half* a_src0 = A + (size_t)(m0 + ar0) * K + ac;
    const __half* a_src1 = A + (size_t)(m0 + ar0 + 64) * K + ac;
    const __half* b_src  = Bt + (size_t)(n0 + br) * K + ac;
    uint32_t a_dst0 = as0 + 2 * (ar0 * ASTR + ac);
    uint32_t a_dst1 = as0 + 2 * ((ar0 + 64) * ASTR + ac);
    uint32_t b_dst  = bs0 + 2 * (br * ASTR + ac);

    float acc[2][4][4];
    #pragma unroll
    for (int i = 0; i < 2; i++)
        #pragma unroll
        for (int j = 0; j < 4; j++)
            #pragma unroll
            for (int q = 0; q < 4; q++) acc[i][j][q] = 0.f;

    cp16(a_dst0, a_src0);
    cp16(a_dst1, a_src1);
    cp16(b_dst, b_src);
    cp_commit();

    #pragma unroll
    for (int kt = 0; kt < KT; kt++) {
        int buf = kt & 1;
        if (kt + 1 < KT) {
            int nb = (kt + 1) & 1;
            int ko = (kt + 1) * 32;
            cp16(a_dst0 + nb * stA, a_src0 + ko);
            cp16(a_dst1 + nb * stA, a_src1 + ko);
            cp16(b_dst + nb * stB, b_src + ko);
            cp_commit();
            cp_wait<1>();
        } else {
            cp_wait<0>();
        }
        __syncthreads();

        uint32_t aoff = buf * stA, boff = buf * stB;
        #pragma unroll
        for (int k16 = 0; k16 < 32; k16 += 16) {
            uint32_t af[2][4], bp[2][4];
            #pragma unroll
            for (int am = 0; am < 2; am++)
                ldsm4(af[am][0], af[am][1], af[am][2], af[am][3],
                      aaddr[am] + aoff + 2 * k16);
            #pragma unroll
            for (int p = 0; p < 2; p++)
                ldsm4(bp[p][0], bp[p][1], bp[p][2], bp[p][3],
                      baddr[p] + boff + 2 * k16);
            #pragma unroll
            for (int am = 0; am < 2; am++)
                #pragma unroll
                for (int an = 0; an < 4; an++) {
                    const uint32_t bfr[2] = {bp[an >> 1][(an & 1) * 2],
                                             bp[an >> 1][(an & 1) * 2 + 1]};
                    mma_f16(acc[am][an], af[am], bfr);
                }
        }
        __syncthreads();
    }

    // store C (fp16 features)
    #pragma unroll
    for (int am = 0; am < 2; am++) {
        int r0 = m0 + warp_m * 32 + am * 16 + g;
        #pragma unroll
        for (int an = 0; an < 4; an++) {
            int cn = n0 + warp_n * 32 + an * 8 + 2 * t;
            if (r0 < M)
                *(__half2*)&g_xwh[(size_t)r0 * N + cn] =
                    __floats2half2_rn(acc[am][an][0], acc[am][an][1]);
            if (r0 + 8 < M)
                *(__half2*)&g_xwh[(size_t)(r0 + 8) * N + cn] =
                    __floats2half2_rn(acc[am][an][2], acc[am][an][3]);
        }
    }

    // fused alpha: dots with a_src/a_dst per row, from fp32 accumulators.
    const float* asv = a_src + h * HID;
    const float* adv = a_dst + h * HID;
    float av[8], dv[8];
    #pragma unroll
    for (int an = 0; an < 4; an++) {
        int c64 = warp_n * 32 + an * 8 + 2 * t;
        av[an * 2 + 0] = asv[c64];     av[an * 2 + 1] = asv[c64 + 1];
        dv[an * 2 + 0] = adv[c64];     dv[an * 2 + 1] = adv[c64 + 1];
    }
    float s1v[2][2] = {}, s2v[2][2] = {};
    #pragma unroll
    for (int am = 0; am < 2; am++)
        #pragma unroll
        for (int an = 0; an < 4; an++) {
            s1v[am][0] += acc[am][an][0] * av[2 * an] + acc[am][an][1] * av[2 * an + 1];
            s1v[am][1] += acc[am][an][2] * av[2 * an] + acc[am][an][3] * av[2 * an + 1];
            s2v[am][0] += acc[am][an][0] * dv[2 * an] + acc[am][an][1] * dv[2 * an + 1];
            s2v[am][1] += acc[am][an][2] * dv[2 * an] + acc[am][an][3] * dv[2 * an + 1];
        }
    #pragma unroll
    for (int mask = 1; mask <= 2; mask <<= 1)
        #pragma unroll
        for (int am = 0; am < 2; am++)
            #pragma unroll
            for (int lh = 0; lh < 2; lh++) {
                s1v[am][lh] += __shfl_xor_sync(0xffffffffu, s1v[am][lh], mask);
                s2v[am][lh] += __shfl_xor_sync(0xffffffffu, s2v[am][lh], mask);
            }
    if (t == 0) {
        #pragma unroll
        for (int am = 0; am < 2; am++)
            #pragma unroll
            for (int lh = 0; lh < 2; lh++) {
                int r = warp_m * 32 + am * 16 + g + lh * 8;
                s_alpha[r][warp_n][0] = s1v[am][lh];
                s_alpha[r][warp_n][1] = s2v[am][lh];
            }
    }
    __syncthreads();
    if (tid < 128) {
        int n = m0 + tid;
        if (n < M) {
            g_asrc[n * H + h] = s_alpha[tid][0][0] + s_alpha[tid][1][0];
            g_adst[n * H + h] = s_alpha[tid][0][1] + s_alpha[tid][1][1];
        }
    }
}

// ---------------- layer-1 aggregate: 3 heads per warp, 4-edge batched gather ----------------
__global__ __launch_bounds__(256)
void aggregate3_kernel(const float* __restrict__ bias) {
    int n = (blockIdx.x * blockDim.x + threadIdx.x) >> 5;
    int lane = threadIdx.x & 31;
    if (n >= N_NODES) return;
    int beg = g_offsets[n], end = g_offsets[n + 1];
    float ad0 = g_adst[n * 3 + 0];
    float ad1 = g_adst[n * 3 + 1];
    float ad2 = g_adst[n * 3 + 2];

    float2 a0 = make_float2(0.f, 0.f), a1 = a0, a2 = a0;
    float d0 = 0.f, d1 = 0.f, d2 = 0.f;
    const __half* xwh = g_xwh;

    for (int base = beg; base < end; base += 32) {
        int j = base + lane;
        bool valid = j < end;
        int s = valid ? g_csr_src[j] : 0;
        float e0 = 0.f, e1 = 0.f, e2 = 0.f;
        if (valid) {
            const float* ap = &g_asrc[s * 3];
            float v0 = ap[0] + ad0, v1 = ap[1] + ad1, v2 = ap[2] + ad2;
            v0 = (v0 > 0.f) ? v0 : SLOPE * v0;
            v1 = (v1 > 0.f) ? v1 : SLOPE * v1;
            v2 = (v2 > 0.f) ? v2 : SLOPE * v2;
            e0 = __expf(v0); e1 = __expf(v1); e2 = __expf(v2);
        }
        d0 += e0; d1 += e1; d2 += e2;
        int ne = min(32, end - base);
        int jj = 0;
        for (; jj + 4 <= ne; jj += 4) {
            int sv[4]; float ev0[4], ev1[4], ev2[4];
            #pragma unroll
            for (int q = 0; q < 4; q++) {
                sv[q]  = __shfl_sync(0xffffffffu, s,  jj + q);
                ev0[q] = __shfl_sync(0xffffffffu, e0, jj + q);
                ev1[q] = __shfl_sync(0xffffffffu, e1, jj + q);
                ev2[q] = __shfl_sync(0xffffffffu, e2, jj + q);
            }
            float2 f0[4], f1[4], f2[4];
            #pragma unroll
            for (int q = 0; q < 4; q++) {
                const __half* r = &xwh[(size_t)sv[q] * 192 + 2 * lane];
                f0[q] = __half22float2(*(const __half2*)(r));
                f1[q] = __half22float2(*(const __half2*)(r + 64));
                f2[q] = __half22float2(*(const __half2*)(r + 128));
            }
            #pragma unroll
            for (int q = 0; q < 4; q++) {
                a0.x += ev0[q] * f0[q].x;  a0.y += ev0[q] * f0[q].y;
                a1.x += ev1[q] * f1[q].x;  a1.y += ev1[q] * f1[q].y;
                a2.x += ev2[q] * f2[q].x;  a2.y += ev2[q] * f2[q].y;
            }
        }
        for (; jj < ne; jj++) {
            int   sA  = __shfl_sync(0xffffffffu, s,  jj);
            float eA0 = __shfl_sync(0xffffffffu, e0, jj);
            float eA1 = __shfl_sync(0xffffffffu, e1, jj);
            float eA2 = __shfl_sync(0xffffffffu, e2, jj);
            const __half* rA = &xwh[(size_t)sA * 192 + 2 * lane];
            float2 fA0 = __half22float2(*(const __half2*)(rA));
            float2 fA1 = __half22float2(*(const __half2*)(rA + 64));
            float2 fA2 = __half22float2(*(const __half2*)(rA + 128));
            a0.x += eA0 * fA0.x;  a0.y += eA0 * fA0.y;
            a1.x += eA1 * fA1.x;  a1.y += eA1 * fA1.y;
            a2.x += eA2 * fA2.x;  a2.y += eA2 * fA2.y;
        }
    }
    #pragma unroll
    for (int o = 16; o > 0; o >>= 1) {
        d0 += __shfl_xor_sync(0xffffffffu, d0, o);
        d1 += __shfl_xor_sync(0xffffffffu, d1, o);
        d2 += __shfl_xor_sync(0xffffffffu, d2, o);
    }
    float i0 = 1.f / (d0 + EPS), i1 = 1.f / (d1 + EPS), i2 = 1.f / (d2 + EPS);
    int c = 2 * lane;
    __half* orow = &g_h1h[(size_t)n * 192];
    *(__half2*)&orow[c] = __floats2half2_rn(
        fmaxf(a0.x * i0 + bias[c], 0.f),       fmaxf(a0.y * i0 + bias[c + 1], 0.f));
    *(__half2*)&orow[c + 64] = __floats2half2_rn(
        fmaxf(a1.x * i1 + bias[c + 64], 0.f),  fmaxf(a1.y * i1 + bias[c + 65], 0.f));
    *(__half2*)&orow[c + 128] = __floats2half2_rn(
        fmaxf(a2.x * i2 + bias[c + 128], 0.f), fmaxf(a2.y * i2 + bias[c + 129], 0.f));
}

// ---------------- layer-2 aggregate: H=1, 8-edge batched gather, fp32 out ----------------
__global__ __launch_bounds__(256)
void aggregate1_kernel(const float* __restrict__ bias, float* __restrict__ out) {
    int n = (blockIdx.x * blockDim.x + threadIdx.x) >> 5;
    int lane = threadIdx.x & 31;
    if (n >= N_NODES) return;
    int beg = g_offsets[n], end = g_offsets[n + 1];
    float adst_n = g_adst[n];

    float2 acc = make_float2(0.f, 0.f);
    float denom = 0.f;
    const __half* xwh = g_xwh;

    for (int base = beg; base < end; base += 32) {
        int j = base + lane;
        bool valid = j < end;
        int s = valid ? g_csr_src[j] : 0;
        float e = 0.f;
        if (valid) {
            float v = g_asrc[s] + adst_n;
            v = (v > 0.f) ? v : SLOPE * v;
            e = __expf(v);
        }
        denom += e;
        int ne = min(32, end - base);
        int jj = 0;
        for (; jj + 8 <= ne; jj += 8) {
            float ev[8]; int sv[8];
            #pragma unroll
            for (int q = 0; q < 8; q++) {
                ev[q] = __shfl_sync(0xffffffffu, e, jj + q);
                sv[q] = __shfl_sync(0xffffffffu, s, jj + q);
            }
            float2 f[8];
            #pragma unroll
            for (int q = 0; q < 8; q++)
                f[q] = __half22float2(*(const __half2*)&xwh[(size_t)sv[q] * 64 + 2 * lane]);
            #pragma unroll
            for (int q = 0; q < 8; q++) {
                acc.x += ev[q] * f[q].x;
                acc.y += ev[q] * f[q].y;
            }
        }
        for (; jj < ne; jj++) {
            float ee = __shfl_sync(0xffffffffu, e, jj);
            int   ss = __shfl_sync(0xffffffffu, s, jj);
            float2 f = __half22float2(*(const __half2*)&xwh[(size_t)ss * 64 + 2 * lane]);
            acc.x += ee * f.x; acc.y += ee * f.y;
        }
    }
    #pragma unroll
    for (int o = 16; o > 0; o >>= 1)
        denom += __shfl_xor_sync(0xffffffffu, denom, o);
    float inv = 1.f / (denom + EPS);
    int c = 2 * lane;
    *(float2*)&out[(size_t)n * 64 + c] = make_float2(
        fmaxf(acc.x * inv + bias[c], 0.f), fmaxf(acc.y * inv + bias[c + 1], 0.f));
}

// ---------------- launch ----------------
extern "C" void kernel_launch(void* const* d_in, const int* in_sizes, int n_in,
                              void* d_out, int out_size) {
    const float* x   = (const float*)d_in[0];
    const void*  ei  = d_in[1];
    const float* W1  = (const float*)d_in[2];
    const float* as1 = (const float*)d_in[3];
    const float* ad1 = (const float*)d_in[4];
    const float* b1  = (const float*)d_in[5];
    const float* W2  = (const float*)d_in[6];
    const float* as2 = (const float*)d_in[7];
    const float* ad2 = (const float*)d_in[8];
    const float* b2  = (const float*)d_in[9];
    float*       out = (float*)d_out;

    const int TB = 256;
    int gridE = (ET + TB - 1) / TB;

    // side stream + fork/join events (host objects only; created twice total)
    cudaStream_t s2;
    cudaStreamCreateWithFlags(&s2, cudaStreamNonBlocking);
    cudaEvent_t evFork, evJoin;
    cudaEventCreateWithFlags(&evFork, cudaEventDisableTiming);
    cudaEventCreateWithFlags(&evJoin, cudaEventDisableTiming);

    // fork immediately: entire CSR chain (incl. its prep) on the side stream
    cudaEventRecord(evFork, 0);
    cudaStreamWaitEvent(s2, evFork, 0);
    prep_side_kernel<<<1 + ZBLK, 256, 0, s2>>>((const int*)ei);
    count_kernel<<<gridE, TB, 0, s2>>>(ei);
    scan_part_kernel<<<NBLK, SCAN_BLK, 0, s2>>>();
    scan_fixup_kernel<<<NBLK, SCAN_BLK, 0, s2>>>();
    scatter_kernel<<<gridE, TB, 0, s2>>>(ei);
    cudaEventRecord(evJoin, s2);

    // main: converts -> GEMM1 (alpha fused), overlapped with CSR
    prep_main_kernel<<<XBLK + WBLK, 256>>>(x, W1, W2);
    {
        dim3 g(M_PAD / 128, (HEADS * HID) / 64);
        gemm_h_kernel<1><<<g, 256>>>(as1, ad1);
    }

    // join, then serial tail
    cudaStreamWaitEvent(0, evJoin, 0);
    aggregate3_kernel<<<(N_NODES + 7) / 8, 256>>>(b1);
    {
        dim3 g(M_PAD / 128, HID / 64);
        gemm_h_kernel<2><<<g, 256>>>(as2, ad2);
    }
    aggregate1_kernel<<<(N_NODES + 7) / 8, 256>>>(b2, out);
}

// round 17
// speedup vs baseline: 1.1296x; 1.1296x over previous
#include <cuda_runtime.h>
#include <cuda_fp16.h>
#include <cstdint>
#include <cstddef>

#define N_NODES 50000
#define M_PAD   50048    // 391 * 128
#define NE      640000
#define ET      (NE + N_NODES)
#define D_IN    128
#define HID     64
#define HEADS   3
#define SLOPE   0.2f
#define EPS     1e-16f

#define SCAN_BLK 1024
#define NBLK     ((N_NODES + SCAN_BLK - 1) / SCAN_BLK)   // 49
#define ASTR     40      // smem row stride in halves (80 B)

// prep block ranges
#define XBLK ((N_NODES * D_IN / 4 + 255) / 256)          // convert x
#define WBLK (((HEADS * HID) * D_IN + 255) / 256)        // convert W
#define ZBLK ((N_NODES + 255) / 256)                     // zero counts

// ---------------- scratch (referenced ONLY from device code) ----------------
__device__ __half g_xh[(size_t)M_PAD * D_IN];
__device__ __half g_w1t[(HEADS * HID) * D_IN];
__device__ __half g_w2t[HID * (HEADS * HID)];
__device__ __half g_xwh[(size_t)N_NODES * HEADS * HID];
__device__ __half g_h1h[(size_t)M_PAD * HEADS * HID];
__device__ float  g_asrc[N_NODES * HEADS];
__device__ float  g_adst[N_NODES * HEADS];
__device__ int    g_counts[N_NODES];
__device__ int    g_offsets[N_NODES + 1];
__device__ int    g_cursor[N_NODES];
__device__ int    g_csr_src[ET];
__device__ int    g_blocksums[NBLK];
__device__ int    g_is64;

// ---------------- small helpers ----------------
__device__ __forceinline__ uint32_t smem_u32(const void* p) {
    return (uint32_t)__cvta_generic_to_shared(p);
}
__device__ __forceinline__ void cp16(uint32_t dst, const void* src) {
    asm volatile("cp.async.cg.shared.global [%0], [%1], 16;\n" :: "r"(dst), "l"(src));
}
__device__ __forceinline__ void cp_commit() {
    asm volatile("cp.async.commit_group;\n");
}
template <int N> __device__ __forceinline__ void cp_wait() {
    asm volatile("cp.async.wait_group %0;\n" :: "n"(N));
}
__device__ __forceinline__ void ldsm4(uint32_t& r0, uint32_t& r1, uint32_t& r2,
                                      uint32_t& r3, uint32_t addr) {
    asm volatile("ldmatrix.sync.aligned.m8n8.x4.shared.b16 {%0,%1,%2,%3}, [%4];\n"
                 : "=r"(r0), "=r"(r1), "=r"(r2), "=r"(r3) : "r"(addr));
}
__device__ __forceinline__ void mma_f16(float* d, const uint32_t* a, const uint32_t* b) {
    asm volatile(
        "mma.sync.aligned.m16n8k16.row.col.f32.f16.f16.f32 "
        "{%0,%1,%2,%3}, {%4,%5,%6,%7}, {%8,%9}, {%0,%1,%2,%3};\n"
        : "+f"(d[0]), "+f"(d[1]), "+f"(d[2]), "+f"(d[3])
        : "r"(a[0]), "r"(a[1]), "r"(a[2]), "r"(a[3]), "r"(b[0]), "r"(b[1]));
}

__device__ __forceinline__ int edge_at(const void* ei, long long idx) {
    if (g_is64) return (int)((const long long*)ei)[idx];
    return ((const int*)ei)[idx];
}

// ---------------- prep (main stream): convert x + convert W to fp16 ----------------
__global__ void prep_main_kernel(const float* __restrict__ x,
                                 const float* __restrict__ W1,
                                 const float* __restrict__ W2) {
    int b = blockIdx.x;
    int tid = threadIdx.x;
    if (b < XBLK) {
        int i = b * 256 + tid;
        if (i < N_NODES * D_IN / 4) {
            float4 v = *(const float4*)(x + 4 * (size_t)i);
            __half2* d = (__half2*)&g_xh[4 * (size_t)i];
            d[0] = __floats2half2_rn(v.x, v.y);
            d[1] = __floats2half2_rn(v.z, v.w);
        }
    } else {
        int i = (b - XBLK) * 256 + tid;
        if (i < (HEADS * HID) * D_IN) {
            int n = i / D_IN, k = i % D_IN;
            g_w1t[i] = __float2half_rn(W1[(size_t)k * (HEADS * HID) + n]);
        }
        if (i < HID * (HEADS * HID)) {
            int n = i / (HEADS * HID), k = i % (HEADS * HID);
            g_w2t[i] = __float2half_rn(W2[(size_t)k * HID + n]);
        }
    }
}

// ---------------- prep (side stream): probe + zero counts ----------------
__global__ void prep_side_kernel(const int* __restrict__ ei32) {
    int b = blockIdx.x;
    int tid = threadIdx.x;
    if (b == 0) {
        __shared__ int s_or[256];
        int acc = 0;
        for (int i = tid; i < 2048; i += 256) acc |= ei32[2 * i + 1];
        s_or[tid] = acc;
        __syncthreads();
        for (int s = 128; s > 0; s >>= 1) {
            if (tid < s) s_or[tid] |= s_or[tid + s];
            __syncthreads();
        }
        if (tid == 0) g_is64 = (s_or[0] == 0) ? 1 : 0;
    } else {
        int i = (b - 1) * 256 + tid;
        if (i < N_NODES) g_counts[i] = 0;
    }
}

// ---------------- CSR build ----------------
__global__ void count_kernel(const void* __restrict__ ei) {
    int e = blockIdx.x * blockDim.x + threadIdx.x;
    if (e >= ET) return;
    int dst = (e < NE) ? edge_at(ei, (long long)NE + e) : (e - NE);
    atomicAdd(&g_counts[dst], 1);
}

__global__ void scan_part_kernel() {
    __shared__ int warp_sums[32];
    int tid = threadIdx.x, lane = tid & 31, wid = tid >> 5;
    int idx = blockIdx.x * SCAN_BLK + tid;
    int v = (idx < N_NODES) ? g_counts[idx] : 0;
    int x = v;
    #pragma unroll
    for (int o = 1; o < 32; o <<= 1) {
        int y = __shfl_up_sync(0xffffffffu, x, o);
        if (lane >= o) x += y;
    }
    if (lane == 31) warp_sums[wid] = x;
    __syncthreads();
    if (wid == 0) {
        int w = warp_sums[lane];
        #pragma unroll
        for (int o = 1; o < 32; o <<= 1) {
            int y = __shfl_up_sync(0xffffffffu, w, o);
            if (lane >= o) w += y;
        }
        warp_sums[lane] = w;
    }
    __syncthreads();
    int warp_off = (wid > 0) ? warp_sums[wid - 1] : 0;
    int incl = x + warp_off;
    if (idx < N_NODES) g_offsets[idx] = incl - v;
    if (tid == SCAN_BLK - 1) g_blocksums[blockIdx.x] = incl;
}

// fixup with the block-sum scan folded in
__global__ void scan_fixup_kernel() {
    __shared__ int s_base, s_total;
    int tid = threadIdx.x;
    int b = blockIdx.x;
    if (tid < 32) {
        int v  = (tid < NBLK) ? g_blocksums[tid] : 0;
        int v2 = (32 + tid < NBLK) ? g_blocksums[32 + tid] : 0;
        int x = v;
        #pragma unroll
        for (int o = 1; o < 32; o <<= 1) {
            int y = __shfl_up_sync(0xffffffffu, x, o);
            if (tid >= o) x += y;
        }
        int sum0 = __shfl_sync(0xffffffffu, x, 31);
        int y2 = v2;
        #pragma unroll
        for (int o = 1; o < 32; o <<= 1) {
            int y = __shfl_up_sync(0xffffffffu, y2, o);
            if (tid >= o) y2 += y;
        }
        y2 += sum0;
        if (b == 0) {
            if (tid == 0) s_base = 0;
        } else {
            int idx = b - 1;
            int want = (idx < 32) ? idx : idx - 32;
            if (tid == want) s_base = (idx < 32) ? x : y2;
        }
        {
            int idxT = NBLK - 1;
            int wantT = (idxT < 32) ? idxT : idxT - 32;
            if (tid == wantT) s_total = (idxT < 32) ? x : y2;
        }
    }
    __syncthreads();
    int idx = b * SCAN_BLK + tid;
    if (idx < N_NODES) {
        int v = g_offsets[idx] + s_base;
        g_offsets[idx] = v;
        g_cursor[idx] = v;
    }
    if (b == NBLK - 1 && tid == 0) g_offsets[N_NODES] = s_total;
}

__global__ void scatter_kernel(const void* __restrict__ ei) {
    int e = blockIdx.x * blockDim.x + threadIdx.x;
    if (e >= ET) return;
    int src, dst;
    if (e < NE) {
        src = edge_at(ei, e);
        dst = edge_at(ei, (long long)NE + e);
    } else {
        src = e - NE; dst = e - NE;
    }
    int pos = atomicAdd(&g_cursor[dst], 1);
    g_csr_src[pos] = src;
}

// ---------------- fp16 GEMM with cp.async + ldmatrix + FUSED alpha epilogue ----------------
// g_xwh[M,N] = half(A @ Bt^T). Each blockIdx.y covers one head's 64 channels
// (layer1: N=192, 3 heads; layer2: N=64, 1 head), so the per-(node,head) alpha
// dots are computed here from fp32 accumulators and written to g_asrc/g_adst.
template <int LAYER>
__global__ __launch_bounds__(256)
void gemm_h_kernel(const float* __restrict__ a_src, const float* __restrict__ a_dst) {
    constexpr int N = (LAYER == 1) ? HEADS * HID : HID;
    constexpr int K = (LAYER == 1) ? D_IN : HEADS * HID;
    constexpr int H = (LAYER == 1) ? HEADS : 1;
    constexpr int KT = K / 32;
    const __half* A  = (LAYER == 1) ? g_xh : g_h1h;
    const __half* Bt = (LAYER == 1) ? g_w1t : g_w2t;
    constexpr int M = N_NODES;

    __shared__ __half As[2][128 * ASTR];
    __shared__ __half Bs[2][64 * ASTR];
    __shared__ float s_alpha[128][2][2];   // [row][warp_n][s1/s2]
    constexpr uint32_t stA = 128 * ASTR * 2;
    constexpr uint32_t stB = 64 * ASTR * 2;

    int tid = threadIdx.x;
    int lane = tid & 31, wid = tid >> 5;
    int warp_m = wid & 3, warp_n = wid >> 2;
    int m0 = blockIdx.x * 128, n0 = blockIdx.y * 64;
    int h = blockIdx.y;
    int g = lane >> 2, t = lane & 3;

    uint32_t as0 = smem_u32(&As[0][0]);
    uint32_t bs0 = smem_u32(&Bs[0][0]);

    uint32_t aaddr[2], baddr[2];
    #pragma unroll
    for (int am = 0; am < 2; am++)
        aaddr[am] = as0 + 2 * ((warp_m * 32 + am * 16 + ((lane >> 3) & 1) * 8 + (lane & 7)) * ASTR
                               + (lane >> 4) * 8);
    #pragma unroll
    for (int p = 0; p < 2; p++)
        baddr[p] = bs0 + 2 * ((warp_n * 32 + p * 16 + (lane >> 4) * 8 + (lane & 7)) * ASTR
                              + ((lane >> 3) & 1) * 8);

    int ar0 = tid >> 2;
    int ac  = (tid & 3) * 8;
    int br  = tid >> 2;
    const __half* a_src0 = A + (size_t)(m0 + ar0) * K + ac;
    const __half* a_src1 = A + (size_t)(m0 + ar0 + 64) * K + ac;
    const __half* b_src  = Bt + (size_t)(n0 + br) * K + ac;
    uint32_t a_dst0 = as0 + 2 * (ar0 * ASTR + ac);
    uint32_t a_dst1 = as0 + 2 * ((ar0 + 64) * ASTR + ac);
    uint32_t b_dst  = bs0 + 2 * (br * ASTR + ac);

    float acc[2][4][4];
    #pragma unroll
    for (int i = 0; i < 2; i++)
        #pragma unroll
        for (int j = 0; j < 4; j++)
            #pragma unroll
            for (int q = 0; q < 4; q++) acc[i][j][q] = 0.f;

    cp16(a_dst0, a_src0);
    cp16(a_dst1, a_src1);
    cp16(b_dst, b_src);
    cp_commit();

    #pragma unroll
    for (int kt = 0; kt < KT; kt++) {
        int buf = kt & 1;
        if (kt + 1 < KT) {
            int nb = (kt + 1) & 1;
            int ko = (kt + 1) * 32;
            cp16(a_dst0 + nb * stA, a_src0 + ko);
            cp16(a_dst1 + nb * stA, a_src1 + ko);
            cp16(b_dst + nb * stB, b_src + ko);
            cp_commit();
            cp_wait<1>();
        } else {
            cp_wait<0>();
        }
        __syncthreads();

        uint32_t aoff = buf * stA, boff = buf * stB;
        #pragma unroll
        for (int k16 = 0; k16 < 32; k16 += 16) {
            uint32_t af[2][4], bp[2][4];
            #pragma unroll
            for (int am = 0; am < 2; am++)
                ldsm4(af[am][0], af[am][1], af[am][2], af[am][3],
                      aaddr[am] + aoff + 2 * k16);
            #pragma unroll
            for (int p = 0; p < 2; p++)
                ldsm4(bp[p][0], bp[p][1], bp[p][2], bp[p][3],
                      baddr[p] + boff + 2 * k16);
            #pragma unroll
            for (int am = 0; am < 2; am++)
                #pragma unroll
                for (int an = 0; an < 4; an++) {
                    const uint32_t bfr[2] = {bp[an >> 1][(an & 1) * 2],
                                             bp[an >> 1][(an & 1) * 2 + 1]};
                    mma_f16(acc[am][an], af[am], bfr);
                }
        }
        __syncthreads();
    }

    // store C (fp16 features)
    #pragma unroll
    for (int am = 0; am < 2; am++) {
        int r0 = m0 + warp_m * 32 + am * 16 + g;
        #pragma unroll
        for (int an = 0; an < 4; an++) {
            int cn = n0 + warp_n * 32 + an * 8 + 2 * t;
            if (r0 < M)
                *(__half2*)&g_xwh[(size_t)r0 * N + cn] =
                    __floats2half2_rn(acc[am][an][0], acc[am][an][1]);
            if (r0 + 8 < M)
                *(__half2*)&g_xwh[(size_t)(r0 + 8) * N + cn] =
                    __floats2half2_rn(acc[am][an][2], acc[am][an][3]);
        }
    }

    // fused alpha: dots with a_src/a_dst per row, from fp32 accumulators.
    const float* asv = a_src + h * HID;
    const float* adv = a_dst + h * HID;
    float av[8], dv[8];
    #pragma unroll
    for (int an = 0; an < 4; an++) {
        int c64 = warp_n * 32 + an * 8 + 2 * t;
        av[an * 2 + 0] = asv[c64];     av[an * 2 + 1] = asv[c64 + 1];
        dv[an * 2 + 0] = adv[c64];     dv[an * 2 + 1] = adv[c64 + 1];
    }
    float s1v[2][2] = {}, s2v[2][2] = {};
    #pragma unroll
    for (int am = 0; am < 2; am++)
        #pragma unroll
        for (int an = 0; an < 4; an++) {
            s1v[am][0] += acc[am][an][0] * av[2 * an] + acc[am][an][1] * av[2 * an + 1];
            s1v[am][1] += acc[am][an][2] * av[2 * an] + acc[am][an][3] * av[2 * an + 1];
            s2v[am][0] += acc[am][an][0] * dv[2 * an] + acc[am][an][1] * dv[2 * an + 1];
            s2v[am][1] += acc[am][an][2] * dv[2 * an] + acc[am][an][3] * dv[2 * an + 1];
        }
    // reduce over the t-quad (lanes g*4+t)
    #pragma unroll
    for (int mask = 1; mask <= 2; mask <<= 1)
        #pragma unroll
        for (int am = 0; am < 2; am++)
            #pragma unroll
            for (int lh = 0; lh < 2; lh++) {
                s1v[am][lh] += __shfl_xor_sync(0xffffffffu, s1v[am][lh], mask);
                s2v[am][lh] += __shfl_xor_sync(0xffffffffu, s2v[am][lh], mask);
            }
    if (t == 0) {
        #pragma unroll
        for (int am = 0; am < 2; am++)
            #pragma unroll
            for (int lh = 0; lh < 2; lh++) {
                int r = warp_m * 32 + am * 16 + g + lh * 8;
                s_alpha[r][warp_n][0] = s1v[am][lh];
                s_alpha[r][warp_n][1] = s2v[am][lh];
            }
    }
    __syncthreads();
    if (tid < 128) {
        int n = m0 + tid;
        if (n < M) {
            g_asrc[n * H + h] = s_alpha[tid][0][0] + s_alpha[tid][1][0];
            g_adst[n * H + h] = s_alpha[tid][0][1] + s_alpha[tid][1][1];
        }
    }
}

// ---------------- layer-1 aggregate: 3 heads per warp, one warp per node ----------------
__global__ __launch_bounds__(256)
void aggregate3_kernel(const float* __restrict__ bias) {
    int n = (blockIdx.x * blockDim.x + threadIdx.x) >> 5;
    int lane = threadIdx.x & 31;
    if (n >= N_NODES) return;
    int beg = g_offsets[n], end = g_offsets[n + 1];
    float ad0 = g_adst[n * 3 + 0];
    float ad1 = g_adst[n * 3 + 1];
    float ad2 = g_adst[n * 3 + 2];

    float2 a0 = make_float2(0.f, 0.f), a1 = a0, a2 = a0;
    float d0 = 0.f, d1 = 0.f, d2 = 0.f;
    const __half* xwh = g_xwh;

    for (int base = beg; base < end; base += 32) {
        int j = base + lane;
        bool valid = j < end;
        int s = valid ? g_csr_src[j] : 0;
        float e0 = 0.f, e1 = 0.f, e2 = 0.f;
        if (valid) {
            const float* ap = &g_asrc[s * 3];
            float v0 = ap[0] + ad0, v1 = ap[1] + ad1, v2 = ap[2] + ad2;
            v0 = (v0 > 0.f) ? v0 : SLOPE * v0;
            v1 = (v1 > 0.f) ? v1 : SLOPE * v1;
            v2 = (v2 > 0.f) ? v2 : SLOPE * v2;
            e0 = __expf(v0); e1 = __expf(v1); e2 = __expf(v2);
        }
        d0 += e0; d1 += e1; d2 += e2;
        int ne = min(32, end - base);
        int jj = 0;
        for (; jj + 2 <= ne; jj += 2) {
            int   sA  = __shfl_sync(0xffffffffu, s,  jj);
            int   sB  = __shfl_sync(0xffffffffu, s,  jj + 1);
            float eA0 = __shfl_sync(0xffffffffu, e0, jj);
            float eA1 = __shfl_sync(0xffffffffu, e1, jj);
            float eA2 = __shfl_sync(0xffffffffu, e2, jj);
            float eB0 = __shfl_sync(0xffffffffu, e0, jj + 1);
            float eB1 = __shfl_sync(0xffffffffu, e1, jj + 1);
            float eB2 = __shfl_sync(0xffffffffu, e2, jj + 1);
            const __half* rA = &xwh[(size_t)sA * 192 + 2 * lane];
            const __half* rB = &xwh[(size_t)sB * 192 + 2 * lane];
            float2 fA0 = __half22float2(*(const __half2*)(rA));
            float2 fA1 = __half22float2(*(const __half2*)(rA + 64));
            float2 fA2 = __half22float2(*(const __half2*)(rA + 128));
            float2 fB0 = __half22float2(*(const __half2*)(rB));
            float2 fB1 = __half22float2(*(const __half2*)(rB + 64));
            float2 fB2 = __half22float2(*(const __half2*)(rB + 128));
            a0.x += eA0 * fA0.x + eB0 * fB0.x;  a0.y += eA0 * fA0.y + eB0 * fB0.y;
            a1.x += eA1 * fA1.x + eB1 * fB1.x;  a1.y += eA1 * fA1.y + eB1 * fB1.y;
            a2.x += eA2 * fA2.x + eB2 * fB2.x;  a2.y += eA2 * fA2.y + eB2 * fB2.y;
        }
        if (jj < ne) {
            int   sA  = __shfl_sync(0xffffffffu, s,  jj);
            float eA0 = __shfl_sync(0xffffffffu, e0, jj);
            float eA1 = __shfl_sync(0xffffffffu, e1, jj);
            float eA2 = __shfl_sync(0xffffffffu, e2, jj);
            const __half* rA = &xwh[(size_t)sA * 192 + 2 * lane];
            float2 fA0 = __half22float2(*(const __half2*)(rA));
            float2 fA1 = __half22float2(*(const __half2*)(rA + 64));
            float2 fA2 = __half22float2(*(const __half2*)(rA + 128));
            a0.x += eA0 * fA0.x;  a0.y += eA0 * fA0.y;
            a1.x += eA1 * fA1.x;  a1.y += eA1 * fA1.y;
            a2.x += eA2 * fA2.x;  a2.y += eA2 * fA2.y;
        }
    }
    #pragma unroll
    for (int o = 16; o > 0; o >>= 1) {
        d0 += __shfl_xor_sync(0xffffffffu, d0, o);
        d1 += __shfl_xor_sync(0xffffffffu, d1, o);
        d2 += __shfl_xor_sync(0xffffffffu, d2, o);
    }
    float i0 = 1.f / (d0 + EPS), i1 = 1.f / (d1 + EPS), i2 = 1.f / (d2 + EPS);
    int c = 2 * lane;
    __half* orow = &g_h1h[(size_t)n * 192];
    *(__half2*)&orow[c] = __floats2half2_rn(
        fmaxf(a0.x * i0 + bias[c], 0.f),       fmaxf(a0.y * i0 + bias[c + 1], 0.f));
    *(__half2*)&orow[c + 64] = __floats2half2_rn(
        fmaxf(a1.x * i1 + bias[c + 64], 0.f),  fmaxf(a1.y * i1 + bias[c + 65], 0.f));
    *(__half2*)&orow[c + 128] = __floats2half2_rn(
        fmaxf(a2.x * i2 + bias[c + 128], 0.f), fmaxf(a2.y * i2 + bias[c + 129], 0.f));
}

// ---------------- layer-2 aggregate: H=1, one warp per node, fp32 out ----------------
__global__ __launch_bounds__(256)
void aggregate1_kernel(const float* __restrict__ bias, float* __restrict__ out) {
    int n = (blockIdx.x * blockDim.x + threadIdx.x) >> 5;
    int lane = threadIdx.x & 31;
    if (n >= N_NODES) return;
    int beg = g_offsets[n], end = g_offsets[n + 1];
    float adst_n = g_adst[n];

    float2 acc = make_float2(0.f, 0.f);
    float denom = 0.f;
    const __half* xwh = g_xwh;

    for (int base = beg; base < end; base += 32) {
        int j = base + lane;
        bool valid = j < end;
        int s = valid ? g_csr_src[j] : 0;
        float e = 0.f;
        if (valid) {
            float v = g_asrc[s] + adst_n;
            v = (v > 0.f) ? v : SLOPE * v;
            e = __expf(v);
        }
        denom += e;
        int ne = min(32, end - base);
        int jj = 0;
        for (; jj + 4 <= ne; jj += 4) {
            float ev[4]; int sv[4];
            #pragma unroll
            for (int q = 0; q < 4; q++) {
                ev[q] = __shfl_sync(0xffffffffu, e, jj + q);
                sv[q] = __shfl_sync(0xffffffffu, s, jj + q);
            }
            float2 f[4];
            #pragma unroll
            for (int q = 0; q < 4; q++)
                f[q] = __half22float2(*(const __half2*)&xwh[(size_t)sv[q] * 64 + 2 * lane]);
            #pragma unroll
            for (int q = 0; q < 4; q++) {
                acc.x += ev[q] * f[q].x;
                acc.y += ev[q] * f[q].y;
            }
        }
        for (; jj < ne; jj++) {
            float ee = __shfl_sync(0xffffffffu, e, jj);
            int   ss = __shfl_sync(0xffffffffu, s, jj);
            float2 f = __half22float2(*(const __half2*)&xwh[(size_t)ss * 64 + 2 * lane]);
            acc.x += ee * f.x; acc.y += ee * f.y;
        }
    }
    #pragma unroll
    for (int o = 16; o > 0; o >>= 1)
        denom += __shfl_xor_sync(0xffffffffu, denom, o);
    float inv = 1.f / (denom + EPS);
    int c = 2 * lane;
    *(float2*)&out[(size_t)n * 64 + c] = make_float2(
        fmaxf(acc.x * inv + bias[c], 0.f), fmaxf(acc.y * inv + bias[c + 1], 0.f));
}

// ---------------- launch ----------------
extern "C" void kernel_launch(void* const* d_in, const int* in_sizes, int n_in,
                              void* d_out, int out_size) {
    const float* x   = (const float*)d_in[0];
    const void*  ei  = d_in[1];
    const float* W1  = (const float*)d_in[2];
    const float* as1 = (const float*)d_in[3];
    const float* ad1 = (const float*)d_in[4];
    const float* b1  = (const float*)d_in[5];
    const float* W2  = (const float*)d_in[6];
    const float* as2 = (const float*)d_in[7];
    const float* ad2 = (const float*)d_in[8];
    const float* b2  = (const float*)d_in[9];
    float*       out = (float*)d_out;

    const int TB = 256;
    int gridE = (ET + TB - 1) / TB;

    // side stream + fork/join events (host objects only; created twice total)
    cudaStream_t s2;
    cudaStreamCreateWithFlags(&s2, cudaStreamNonBlocking);
    cudaEvent_t evFork, evJoin;
    cudaEventCreateWithFlags(&evFork, cudaEventDisableTiming);
    cudaEventCreateWithFlags(&evJoin, cudaEventDisableTiming);

    // fork immediately: entire CSR chain (incl. its prep) on the side stream
    cudaEventRecord(evFork, 0);
    cudaStreamWaitEvent(s2, evFork, 0);
    prep_side_kernel<<<1 + ZBLK, 256, 0, s2>>>((const int*)ei);
    count_kernel<<<gridE, TB, 0, s2>>>(ei);
    scan_part_kernel<<<NBLK, SCAN_BLK, 0, s2>>>();
    scan_fixup_kernel<<<NBLK, SCAN_BLK, 0, s2>>>();
    scatter_kernel<<<gridE, TB, 0, s2>>>(ei);
    cudaEventRecord(evJoin, s2);

    // main: converts -> GEMM1 (alpha fused), overlapped with CSR
    prep_main_kernel<<<XBLK + WBLK, 256>>>(x, W1, W2);
    {
        dim3 g(M_PAD / 128, (HEADS * HID) / 64);
        gemm_h_kernel<1><<<g, 256>>>(as1, ad1);
    }

    // join, then serial tail
    cudaStreamWaitEvent(0, evJoin, 0);
    aggregate3_kernel<<<(N_NODES + 7) / 8, 256>>>(b1);
    {
        dim3 g(M_PAD / 128, HID / 64);
        gemm_h_kernel<2><<<g, 256>>>(as2, ad2);
    }
    aggregate1_kernel<<<(N_NODES + 7) / 8, 256>>>(b2, out);
}